// round 1
// baseline (speedup 1.0000x reference)
#include <cuda_runtime.h>

#define EN 200000
#define NN 25000

typedef unsigned long long ull;

// ---------------- scratch (static device arrays; no allocations) ----------------
__device__ float g_qs[NN * 8];
__device__ float g_qv[NN * 24];
__device__ float g_expv[EN];
__device__ float g_vbuf[32 * EN];   // field-major: [field][edge] for coalescing
__device__ float g_zsum[NN];
__device__ float g_cnt[NN];

// ---------------- packed f32x2 helpers (sm_103a) ----------------
__device__ __forceinline__ ull pack2(float x) {
    ull r; asm("mov.b64 %0, {%1, %1};" : "=l"(r) : "f"(x)); return r;
}
__device__ __forceinline__ void fma2(ull &acc, ull a, ull b) {
    asm("fma.rn.f32x2 %0, %1, %2, %0;" : "+l"(acc) : "l"(a), "l"(b));
}
__device__ __forceinline__ void unpack2(ull v, float &lo, float &hi) {
    asm("mov.b64 {%0, %1}, %2;" : "=f"(lo), "=f"(hi) : "l"(v));
}

// ---------------- radial MLP + tensor-product contraction (fused) ----------------
// Computes, for one radial (W1: [16,64], W2: [64,320] row-major):
//   S[n]    = sum_m wraw[0][m][n]*xss[m] + wraw[3][m][n]*dt[m]
//   T1[n]   = sum_m wraw[1][m][n]*xs[m]
//   T24[n][c] = sum_m wraw[2][m][n]*xvs[m][c] + wraw[4][m][n]*crs[m][c]
// where wraw = silu(ea@W1*0.25) @ W2   (w-scale 1/8 applied by caller)
__device__ __forceinline__ void radial_tp(
    const float* __restrict__ W1, const float* __restrict__ W2,
    const float* ea, const float* xs, const float* xss, const float* dt,
    const float (*xvs)[3], const float (*crs)[3],
    float* oS, float* oT1, float (*oT24)[3])
{
    ull Us[4]  = {0, 0, 0, 0};
    ull Ut1[4] = {0, 0, 0, 0};
    ull Ut24[4][3] = {{0,0,0},{0,0,0},{0,0,0},{0,0,0}};

    #pragma unroll 1
    for (int c0 = 0; c0 < 64; c0 += 16) {
        // hidden activations for this chunk, packed {h,h}
        ull h2[16];
        #pragma unroll
        for (int j = 0; j < 16; j++) {
            float s = 0.f;
            #pragma unroll
            for (int i = 0; i < 16; i++)
                s = fmaf(ea[i], __ldg(W1 + i * 64 + c0 + j), s);
            s *= 0.25f;                                   // 1/sqrt(16)
            float h = __fdividef(s, 1.f + __expf(-s));    // silu
            h2[j] = pack2(h);
        }
        #pragma unroll
        for (int p = 0; p < 5; p++) {
            #pragma unroll
            for (int m = 0; m < 8; m++) {
                const double2* wp =
                    reinterpret_cast<const double2*>(W2 + c0 * 320 + p * 64 + m * 8);
                ull w0 = 0, w1 = 0, w2 = 0, w3 = 0;   // n-pairs (0,1)(2,3)(4,5)(6,7)
                #pragma unroll
                for (int j = 0; j < 16; j++) {
                    double2 d0 = __ldg(wp + j * 80);       // 320 floats/row = 80 double2
                    double2 d1 = __ldg(wp + j * 80 + 1);
                    fma2(w0, h2[j], __double_as_longlong(d0.x));
                    fma2(w1, h2[j], __double_as_longlong(d0.y));
                    fma2(w2, h2[j], __double_as_longlong(d1.x));
                    fma2(w3, h2[j], __double_as_longlong(d1.y));
                }
                if (p == 0) {
                    ull a = pack2(xss[m]);
                    fma2(Us[0], w0, a); fma2(Us[1], w1, a); fma2(Us[2], w2, a); fma2(Us[3], w3, a);
                } else if (p == 1) {
                    ull a = pack2(xs[m]);
                    fma2(Ut1[0], w0, a); fma2(Ut1[1], w1, a); fma2(Ut1[2], w2, a); fma2(Ut1[3], w3, a);
                } else if (p == 3) {
                    ull a = pack2(dt[m]);
                    fma2(Us[0], w0, a); fma2(Us[1], w1, a); fma2(Us[2], w2, a); fma2(Us[3], w3, a);
                } else if (p == 2) {
                    #pragma unroll
                    for (int c = 0; c < 3; c++) {
                        ull a = pack2(xvs[m][c]);
                        fma2(Ut24[0][c], w0, a); fma2(Ut24[1][c], w1, a);
                        fma2(Ut24[2][c], w2, a); fma2(Ut24[3][c], w3, a);
                    }
                } else { // p == 4
                    #pragma unroll
                    for (int c = 0; c < 3; c++) {
                        ull a = pack2(crs[m][c]);
                        fma2(Ut24[0][c], w0, a); fma2(Ut24[1][c], w1, a);
                        fma2(Ut24[2][c], w2, a); fma2(Ut24[3][c], w3, a);
                    }
                }
            }
        }
    }
    #pragma unroll
    for (int q = 0; q < 4; q++) {
        unpack2(Us[q],  oS[2*q],  oS[2*q+1]);
        unpack2(Ut1[q], oT1[2*q], oT1[2*q+1]);
        #pragma unroll
        for (int c = 0; c < 3; c++)
            unpack2(Ut24[q][c], oT24[2*q][c], oT24[2*q+1][c]);
    }
}

// ---------------- kernel 0: zero init ----------------
__global__ void zero_kernel(float* __restrict__ out) {
    int i = blockIdx.x * blockDim.x + threadIdx.x;
    if (i < NN * 32) out[i] = 0.f;
    if (i < NN) { g_zsum[i] = 0.f; g_cnt[i] = 0.f; }
}

// ---------------- kernel 1: node projections qs, qv ----------------
__global__ void node_kernel(const float* __restrict__ node_attr,
                            const float* __restrict__ Wq0,
                            const float* __restrict__ Wq1)
{
    int n = blockIdx.x * blockDim.x + threadIdx.x;
    if (n >= NN) return;
    float na[32];
    const float4* p = reinterpret_cast<const float4*>(node_attr + (size_t)n * 32);
    #pragma unroll
    for (int q = 0; q < 8; q++) {
        float4 v = __ldg(p + q);
        na[4*q] = v.x; na[4*q+1] = v.y; na[4*q+2] = v.z; na[4*q+3] = v.w;
    }
    const float im = 0.35355339059327373f;  // 1/sqrt(8)
    #pragma unroll
    for (int k = 0; k < 8; k++) {
        float a = 0.f;
        #pragma unroll
        for (int m = 0; m < 8; m++) a = fmaf(na[m], __ldg(Wq0 + m * 8 + k), a);
        g_qs[n * 8 + k] = a * im;
    }
    #pragma unroll
    for (int k = 0; k < 8; k++) {
        float a0 = 0.f, a1 = 0.f, a2 = 0.f;
        #pragma unroll
        for (int m = 0; m < 8; m++) {
            float w = __ldg(Wq1 + m * 8 + k);
            a0 = fmaf(na[8 + 3*m],  w, a0);
            a1 = fmaf(na[9 + 3*m],  w, a1);
            a2 = fmaf(na[10 + 3*m], w, a2);
        }
        g_qv[n * 24 + 3*k]     = a0 * im;
        g_qv[n * 24 + 3*k + 1] = a1 * im;
        g_qv[n * 24 + 3*k + 2] = a2 * im;
    }
}

// ---------------- kernel 2: per-edge heavy compute ----------------
__global__ __launch_bounds__(256, 1) void edge_kernel(
    const float* __restrict__ node_attr, const int* __restrict__ ei,
    const float* __restrict__ edge_attr, const float* __restrict__ edge_sh,
    const float* __restrict__ kW1, const float* __restrict__ kW2,
    const float* __restrict__ vW1, const float* __restrict__ vW2,
    const float* __restrict__ Wd0, const float* __restrict__ Wd1)
{
    int e = blockIdx.x * blockDim.x + threadIdx.x;
    if (e >= EN) return;
    int src = __ldg(ei + e);
    int dst = __ldg(ei + EN + e);

    float ea[16];
    {
        const float4* p = reinterpret_cast<const float4*>(edge_attr + (size_t)e * 16);
        #pragma unroll
        for (int q = 0; q < 4; q++) {
            float4 v = __ldg(p + q);
            ea[4*q] = v.x; ea[4*q+1] = v.y; ea[4*q+2] = v.z; ea[4*q+3] = v.w;
        }
    }
    float4 sh = __ldg(reinterpret_cast<const float4*>(edge_sh + (size_t)e * 4));
    float s0 = sh.x, s1x = sh.y, s1y = sh.z, s1z = sh.w;

    float na[32];
    {
        const float4* p = reinterpret_cast<const float4*>(node_attr + (size_t)src * 32);
        #pragma unroll
        for (int q = 0; q < 8; q++) {
            float4 v = __ldg(p + q);
            na[4*q] = v.x; na[4*q+1] = v.y; na[4*q+2] = v.z; na[4*q+3] = v.w;
        }
    }

    const float i3 = 0.5773502691896258f;   // 1/sqrt(3)
    const float i2 = 0.7071067811865476f;   // 1/sqrt(2)
    float xs[8], xss[8], dt[8], xvs[8][3], crs[8][3];
    #pragma unroll
    for (int m = 0; m < 8; m++) {
        xs[m]  = na[m];
        xss[m] = na[m] * s0;
        float vx = na[8 + 3*m], vy = na[9 + 3*m], vz = na[10 + 3*m];
        dt[m] = (vx * s1x + vy * s1y + vz * s1z) * i3;
        xvs[m][0] = vx * s0; xvs[m][1] = vy * s0; xvs[m][2] = vz * s0;
        crs[m][0] = (vy * s1z - vz * s1y) * i2;
        crs[m][1] = (vz * s1x - vx * s1z) * i2;
        crs[m][2] = (vx * s1y - vy * s1x) * i2;
    }

    const float c_s = 0.03125f;               // (1/8)*(1/sqrt(16))
    const float c_v = 0.025515518153991442f;  // (1/8)*(1/sqrt(24))

    // ---- V radial: compute, scale, store straight to scratch ----
    {
        float S[8], T1[8], T24[8][3];
        radial_tp(vW1, vW2, ea, xs, xss, dt, xvs, crs, S, T1, T24);
        #pragma unroll
        for (int n = 0; n < 8; n++) g_vbuf[n * EN + e] = S[n] * c_s;
        #pragma unroll
        for (int n = 0; n < 8; n++) {
            g_vbuf[(8 + 3*n + 0) * EN + e] = (T1[n] * s1x + T24[n][0]) * c_v;
            g_vbuf[(8 + 3*n + 1) * EN + e] = (T1[n] * s1y + T24[n][1]) * c_v;
            g_vbuf[(8 + 3*n + 2) * EN + e] = (T1[n] * s1z + T24[n][2]) * c_v;
        }
    }

    // ---- K radial ----
    float ks[8], kv[8][3];
    {
        float S[8], T1[8], T24[8][3];
        radial_tp(kW1, kW2, ea, xs, xss, dt, xvs, crs, S, T1, T24);
        #pragma unroll
        for (int n = 0; n < 8; n++) {
            ks[n]    = S[n] * c_s;
            kv[n][0] = (T1[n] * s1x + T24[n][0]) * c_v;
            kv[n][1] = (T1[n] * s1y + T24[n][1]) * c_v;
            kv[n][2] = (T1[n] * s1z + T24[n][2]) * c_v;
        }
    }

    // ---- logits ----
    float qsd[8], qvd[24];
    {
        const float4* p = reinterpret_cast<const float4*>(g_qs + (size_t)dst * 8);
        float4 a = p[0], b = p[1];
        qsd[0]=a.x; qsd[1]=a.y; qsd[2]=a.z; qsd[3]=a.w;
        qsd[4]=b.x; qsd[5]=b.y; qsd[6]=b.z; qsd[7]=b.w;
    }
    {
        const float4* p = reinterpret_cast<const float4*>(g_qv + (size_t)dst * 24);
        #pragma unroll
        for (int q = 0; q < 6; q++) {
            float4 v = p[q];
            qvd[4*q]=v.x; qvd[4*q+1]=v.y; qvd[4*q+2]=v.z; qvd[4*q+3]=v.w;
        }
    }
    float t0 = 0.f, t1 = 0.f;
    #pragma unroll
    for (int m = 0; m < 8; m++) {
        float r = 0.f;
        #pragma unroll
        for (int n = 0; n < 8; n++) r = fmaf(__ldg(Wd0 + m * 8 + n), ks[n], r);
        t0 = fmaf(qsd[m], r, t0);
    }
    #pragma unroll
    for (int m = 0; m < 8; m++) {
        float r = 0.f;
        #pragma unroll
        for (int n = 0; n < 8; n++) {
            float dd = qvd[3*m] * kv[n][0] + qvd[3*m+1] * kv[n][1] + qvd[3*m+2] * kv[n][2];
            r = fmaf(__ldg(Wd1 + m * 8 + n), dd, r);
        }
        t1 += r;
    }
    float logit = (t0 + t1 * i3) * 0.25f;
    float ex = __expf(logit);
    g_expv[e] = ex;
    atomicAdd(&g_zsum[dst], ex);
    atomicAdd(&g_cnt[dst], 1.f);
}

// ---------------- kernel 3: normalize + scatter ----------------
__global__ void scatter_kernel(const int* __restrict__ ei, float* __restrict__ out) {
    int e = blockIdx.x * blockDim.x + threadIdx.x;
    if (e >= EN) return;
    int dst = __ldg(ei + EN + e);
    float ex = g_expv[e];
    float zs = g_zsum[dst];
    float c  = g_cnt[dst];
    float alpha = ex * fmaxf(c, 1.f) / zs;
    float attn = sqrtf(fmaxf(alpha, 0.f));
    float* op = out + (size_t)dst * 32;
    #pragma unroll
    for (int k = 0; k < 32; k++)
        atomicAdd(op + k, attn * g_vbuf[k * EN + e]);
}

// ---------------- launcher ----------------
extern "C" void kernel_launch(void* const* d_in, const int* in_sizes, int n_in,
                              void* d_out, int out_size) {
    const float* node_attr = (const float*)d_in[0];
    const int*   ei        = (const int*)  d_in[1];
    const float* edge_attr = (const float*)d_in[2];
    const float* edge_sh   = (const float*)d_in[3];
    const float* Wq0       = (const float*)d_in[4];
    const float* Wq1       = (const float*)d_in[5];
    const float* kW1       = (const float*)d_in[6];
    const float* kW2       = (const float*)d_in[7];
    const float* vW1       = (const float*)d_in[8];
    const float* vW2       = (const float*)d_in[9];
    const float* Wd0       = (const float*)d_in[10];
    const float* Wd1       = (const float*)d_in[11];
    float* out = (float*)d_out;

    zero_kernel<<<(NN * 32 + 255) / 256, 256>>>(out);
    node_kernel<<<(NN + 127) / 128, 128>>>(node_attr, Wq0, Wq1);
    edge_kernel<<<(EN + 255) / 256, 256>>>(node_attr, ei, edge_attr, edge_sh,
                                           kW1, kW2, vW1, vW2, Wd0, Wd1);
    scatter_kernel<<<(EN + 255) / 256, 256>>>(ei, out);
}

// round 4
// speedup vs baseline: 1.8524x; 1.8524x over previous
#include <cuda_runtime.h>
#include <cstdint>

#define EN 200000
#define NN 25000

typedef unsigned long long ull;

// ---------------- scratch (static device arrays; no allocations) ----------------
__device__ float g_qs[NN * 8];
__device__ float g_qv[NN * 24];
__device__ float g_expv[EN];
__device__ float g_vbuf[32 * EN];   // field-major: [field][edge] for coalescing
__device__ float g_zsum[NN];
__device__ float g_cnt[NN];

// ---------------- packed f32x2 helpers (sm_103a) ----------------
__device__ __forceinline__ ull pack2(float x) {
    ull r; asm("mov.b64 %0, {%1, %1};" : "=l"(r) : "f"(x)); return r;
}
__device__ __forceinline__ void fma2(ull &acc, ull a, ull b) {
    asm("fma.rn.f32x2 %0, %1, %2, %0;" : "+l"(acc) : "l"(a), "l"(b));
}
__device__ __forceinline__ void unpack2(ull v, float &lo, float &hi) {
    asm("mov.b64 {%0, %1}, %2;" : "=f"(lo), "=f"(hi) : "l"(v));
}
__device__ __forceinline__ uint32_t smem_u32(const void* p) {
    return (uint32_t)__cvta_generic_to_shared(p);
}
__device__ __forceinline__ void cpasync16(uint32_t dst, const void* src) {
    asm volatile("cp.async.cg.shared.global [%0], [%1], 16;" :: "r"(dst), "l"(src));
}
__device__ __forceinline__ void cpasync_commit() {
    asm volatile("cp.async.commit_group;");
}
__device__ __forceinline__ void cpasync_wait0() {
    asm volatile("cp.async.wait_group 0;");
}

// ---------------- kernel 0: zero init ----------------
__global__ void zero_kernel(float* __restrict__ out) {
    int i = blockIdx.x * blockDim.x + threadIdx.x;
    if (i < NN * 32) out[i] = 0.f;
    if (i < NN) { g_zsum[i] = 0.f; g_cnt[i] = 0.f; }
}

// ---------------- kernel 1: node projections qs, qv ----------------
__global__ void node_kernel(const float* __restrict__ node_attr,
                            const float* __restrict__ Wq0,
                            const float* __restrict__ Wq1)
{
    int n = blockIdx.x * blockDim.x + threadIdx.x;
    if (n >= NN) return;
    float na[32];
    const float4* p = reinterpret_cast<const float4*>(node_attr + (size_t)n * 32);
    #pragma unroll
    for (int q = 0; q < 8; q++) {
        float4 v = __ldg(p + q);
        na[4*q] = v.x; na[4*q+1] = v.y; na[4*q+2] = v.z; na[4*q+3] = v.w;
    }
    const float im = 0.35355339059327373f;  // 1/sqrt(8)
    #pragma unroll
    for (int k = 0; k < 8; k++) {
        float a = 0.f;
        #pragma unroll
        for (int m = 0; m < 8; m++) a = fmaf(na[m], __ldg(Wq0 + m * 8 + k), a);
        g_qs[n * 8 + k] = a * im;
    }
    #pragma unroll
    for (int k = 0; k < 8; k++) {
        float a0 = 0.f, a1 = 0.f, a2 = 0.f;
        #pragma unroll
        for (int m = 0; m < 8; m++) {
            float w = __ldg(Wq1 + m * 8 + k);
            a0 = fmaf(na[8 + 3*m],  w, a0);
            a1 = fmaf(na[9 + 3*m],  w, a1);
            a2 = fmaf(na[10 + 3*m], w, a2);
        }
        g_qv[n * 24 + 3*k]     = a0 * im;
        g_qv[n * 24 + 3*k + 1] = a1 * im;
        g_qv[n * 24 + 3*k + 2] = a2 * im;
    }
}

// ---------------- kernel 2: per-edge heavy compute (smem-staged weights) ----------------
__global__ __launch_bounds__(256, 1) void edge_kernel(
    const float* __restrict__ node_attr, const int* __restrict__ ei,
    const float* __restrict__ edge_attr, const float* __restrict__ edge_sh,
    const float* __restrict__ kW1, const float* __restrict__ kW2,
    const float* __restrict__ vW1, const float* __restrict__ vW2,
    const float* __restrict__ Wd0, const float* __restrict__ Wd1)
{
    __shared__ float sW2[2][16 * 320];   // 2 x 20KB double buffer
    __shared__ float sW1[2][16 * 64];    // [0]=vW1, [1]=kW1  (8KB)

    int tid = threadIdx.x;
    int e = blockIdx.x * 256 + tid;
    bool active = e < EN;
    int ee = active ? e : 0;

    // stage W1 for both radials (once)
    #pragma unroll
    for (int i = tid; i < 1024; i += 256) {
        sW1[0][i] = __ldg(vW1 + i);
        sW1[1][i] = __ldg(kW1 + i);
    }

    // prefetch W2 chunk 0 (vW2 rows 0..15) into buffer 0
    uint32_t sb0 = smem_u32(sW2[0]);
    uint32_t sb1 = smem_u32(sW2[1]);
    {
        const float4* s = reinterpret_cast<const float4*>(vW2);
        #pragma unroll
        for (int k = 0; k < 5; k++)
            cpasync16(sb0 + (uint32_t)(tid + k * 256) * 16, s + tid + k * 256);
        cpasync_commit();
    }

    int src = __ldg(ei + ee);
    int dst = __ldg(ei + EN + ee);

    float ea[16];
    {
        const float4* p = reinterpret_cast<const float4*>(edge_attr + (size_t)ee * 16);
        #pragma unroll
        for (int q = 0; q < 4; q++) {
            float4 v = __ldg(p + q);
            ea[4*q] = v.x; ea[4*q+1] = v.y; ea[4*q+2] = v.z; ea[4*q+3] = v.w;
        }
    }
    float4 sh = __ldg(reinterpret_cast<const float4*>(edge_sh + (size_t)ee * 4));
    float s0 = sh.x, s1x = sh.y, s1y = sh.z, s1z = sh.w;

    float na[32];
    {
        const float4* p = reinterpret_cast<const float4*>(node_attr + (size_t)src * 32);
        #pragma unroll
        for (int q = 0; q < 8; q++) {
            float4 v = __ldg(p + q);
            na[4*q] = v.x; na[4*q+1] = v.y; na[4*q+2] = v.z; na[4*q+3] = v.w;
        }
    }

    const float i3 = 0.5773502691896258f;   // 1/sqrt(3)
    const float i2 = 0.7071067811865476f;   // 1/sqrt(2)
    float xs[8], xss[8], dt[8], xvs[8][3], crs[8][3];
    #pragma unroll
    for (int m = 0; m < 8; m++) {
        xs[m]  = na[m];
        xss[m] = na[m] * s0;
        float vx = na[8 + 3*m], vy = na[9 + 3*m], vz = na[10 + 3*m];
        dt[m] = (vx * s1x + vy * s1y + vz * s1z) * i3;
        xvs[m][0] = vx * s0; xvs[m][1] = vy * s0; xvs[m][2] = vz * s0;
        crs[m][0] = (vy * s1z - vz * s1y) * i2;
        crs[m][1] = (vz * s1x - vx * s1z) * i2;
        crs[m][2] = (vx * s1y - vy * s1x) * i2;
    }

    const float c_s = 0.03125f;               // (1/8)*(1/sqrt(16))
    const float c_v = 0.025515518153991442f;  // (1/8)*(1/sqrt(24))

    ull Us[4]  = {0, 0, 0, 0};
    ull Ut1[4] = {0, 0, 0, 0};
    ull Ut24[4][3] = {{0,0,0},{0,0,0},{0,0,0},{0,0,0}};
    float ks[8], kv[8][3];

    cpasync_wait0();
    __syncthreads();

    int b = 0;
    #pragma unroll 1
    for (int g = 0; g < 8; g++) {
        // prefetch next chunk into the other buffer
        if (g < 7) {
            const float* nsrc = (g < 3) ? (vW2 + (g + 1) * 5120)
                                        : (kW2 + ((g + 1) & 3) * 5120);
            const float4* s = reinterpret_cast<const float4*>(nsrc);
            uint32_t dstb = (b ? sb0 : sb1);
            #pragma unroll
            for (int k = 0; k < 5; k++)
                cpasync16(dstb + (uint32_t)(tid + k * 256) * 16, s + tid + k * 256);
            cpasync_commit();
        }

        int r = g >> 2, c = g & 3;

        // hidden activations for this chunk (16 of 64), packed {h,h}
        const float* w1 = sW1[r] + c * 16;
        ull h2[16];
        #pragma unroll
        for (int j = 0; j < 16; j++) {
            float s = 0.f;
            #pragma unroll
            for (int i = 0; i < 16; i++)
                s = fmaf(ea[i], w1[i * 64 + j], s);
            s *= 0.25f;                                   // 1/sqrt(16)
            float h = __fdividef(s, 1.f + __expf(-s));    // silu
            h2[j] = pack2(h);
        }

        const float* wb = sW2[b];
        #pragma unroll
        for (int p = 0; p < 5; p++) {
            #pragma unroll
            for (int m = 0; m < 8; m++) {
                const double2* wp = reinterpret_cast<const double2*>(wb + p * 64 + m * 8);
                ull w0 = 0, w1a = 0, w2 = 0, w3 = 0;   // n-pairs (0,1)(2,3)(4,5)(6,7)
                #pragma unroll
                for (int j = 0; j < 16; j++) {
                    double2 d0 = wp[j * 80];        // 320 floats/row = 80 double2
                    double2 d1 = wp[j * 80 + 1];
                    fma2(w0,  h2[j], __double_as_longlong(d0.x));
                    fma2(w1a, h2[j], __double_as_longlong(d0.y));
                    fma2(w2,  h2[j], __double_as_longlong(d1.x));
                    fma2(w3,  h2[j], __double_as_longlong(d1.y));
                }
                if (p == 0) {
                    ull a = pack2(xss[m]);
                    fma2(Us[0], w0, a); fma2(Us[1], w1a, a); fma2(Us[2], w2, a); fma2(Us[3], w3, a);
                } else if (p == 1) {
                    ull a = pack2(xs[m]);
                    fma2(Ut1[0], w0, a); fma2(Ut1[1], w1a, a); fma2(Ut1[2], w2, a); fma2(Ut1[3], w3, a);
                } else if (p == 3) {
                    ull a = pack2(dt[m]);
                    fma2(Us[0], w0, a); fma2(Us[1], w1a, a); fma2(Us[2], w2, a); fma2(Us[3], w3, a);
                } else if (p == 2) {
                    #pragma unroll
                    for (int cc = 0; cc < 3; cc++) {
                        ull a = pack2(xvs[m][cc]);
                        fma2(Ut24[0][cc], w0, a); fma2(Ut24[1][cc], w1a, a);
                        fma2(Ut24[2][cc], w2, a); fma2(Ut24[3][cc], w3, a);
                    }
                } else { // p == 4
                    #pragma unroll
                    for (int cc = 0; cc < 3; cc++) {
                        ull a = pack2(crs[m][cc]);
                        fma2(Ut24[0][cc], w0, a); fma2(Ut24[1][cc], w1a, a);
                        fma2(Ut24[2][cc], w2, a); fma2(Ut24[3][cc], w3, a);
                    }
                }
            }
        }

        if (g == 3) {
            // V radial complete: scale, store to scratch, reset accumulators
            #pragma unroll
            for (int q = 0; q < 4; q++) {
                float Slo, Shi, Tlo, Thi;
                unpack2(Us[q], Slo, Shi);
                unpack2(Ut1[q], Tlo, Thi);
                float T24lo[3], T24hi[3];
                #pragma unroll
                for (int cc = 0; cc < 3; cc++)
                    unpack2(Ut24[q][cc], T24lo[cc], T24hi[cc]);
                if (active) {
                    int n0 = 2 * q, n1 = 2 * q + 1;
                    g_vbuf[n0 * EN + e] = Slo * c_s;
                    g_vbuf[n1 * EN + e] = Shi * c_s;
                    g_vbuf[(8 + 3*n0 + 0) * EN + e] = (Tlo * s1x + T24lo[0]) * c_v;
                    g_vbuf[(8 + 3*n0 + 1) * EN + e] = (Tlo * s1y + T24lo[1]) * c_v;
                    g_vbuf[(8 + 3*n0 + 2) * EN + e] = (Tlo * s1z + T24lo[2]) * c_v;
                    g_vbuf[(8 + 3*n1 + 0) * EN + e] = (Thi * s1x + T24hi[0]) * c_v;
                    g_vbuf[(8 + 3*n1 + 1) * EN + e] = (Thi * s1y + T24hi[1]) * c_v;
                    g_vbuf[(8 + 3*n1 + 2) * EN + e] = (Thi * s1z + T24hi[2]) * c_v;
                }
                Us[q] = 0; Ut1[q] = 0;
                Ut24[q][0] = 0; Ut24[q][1] = 0; Ut24[q][2] = 0;
            }
        }
        if (g == 7) {
            // K radial complete: unpack into ks/kv
            #pragma unroll
            for (int q = 0; q < 4; q++) {
                float Slo, Shi, Tlo, Thi;
                unpack2(Us[q], Slo, Shi);
                unpack2(Ut1[q], Tlo, Thi);
                float T24lo[3], T24hi[3];
                #pragma unroll
                for (int cc = 0; cc < 3; cc++)
                    unpack2(Ut24[q][cc], T24lo[cc], T24hi[cc]);
                int n0 = 2 * q, n1 = 2 * q + 1;
                ks[n0] = Slo * c_s;
                ks[n1] = Shi * c_s;
                kv[n0][0] = (Tlo * s1x + T24lo[0]) * c_v;
                kv[n0][1] = (Tlo * s1y + T24lo[1]) * c_v;
                kv[n0][2] = (Tlo * s1z + T24lo[2]) * c_v;
                kv[n1][0] = (Thi * s1x + T24hi[0]) * c_v;
                kv[n1][1] = (Thi * s1y + T24hi[1]) * c_v;
                kv[n1][2] = (Thi * s1z + T24hi[2]) * c_v;
            }
        }

        if (g < 7) {
            cpasync_wait0();
            __syncthreads();
            b ^= 1;
        }
    }

    // ---- logits ----
    float qsd[8], qvd[24];
    {
        const float4* p = reinterpret_cast<const float4*>(g_qs + (size_t)dst * 8);
        float4 a = p[0], bq = p[1];
        qsd[0]=a.x; qsd[1]=a.y; qsd[2]=a.z; qsd[3]=a.w;
        qsd[4]=bq.x; qsd[5]=bq.y; qsd[6]=bq.z; qsd[7]=bq.w;
    }
    {
        const float4* p = reinterpret_cast<const float4*>(g_qv + (size_t)dst * 24);
        #pragma unroll
        for (int q = 0; q < 6; q++) {
            float4 v = p[q];
            qvd[4*q]=v.x; qvd[4*q+1]=v.y; qvd[4*q+2]=v.z; qvd[4*q+3]=v.w;
        }
    }
    float t0 = 0.f, t1 = 0.f;
    #pragma unroll
    for (int m = 0; m < 8; m++) {
        float r = 0.f;
        #pragma unroll
        for (int n = 0; n < 8; n++) r = fmaf(__ldg(Wd0 + m * 8 + n), ks[n], r);
        t0 = fmaf(qsd[m], r, t0);
    }
    #pragma unroll
    for (int m = 0; m < 8; m++) {
        float r = 0.f;
        #pragma unroll
        for (int n = 0; n < 8; n++) {
            float dd = qvd[3*m] * kv[n][0] + qvd[3*m+1] * kv[n][1] + qvd[3*m+2] * kv[n][2];
            r = fmaf(__ldg(Wd1 + m * 8 + n), dd, r);
        }
        t1 += r;
    }
    float logit = (t0 + t1 * i3) * 0.25f;
    float ex = __expf(logit);
    if (active) {
        g_expv[e] = ex;
        atomicAdd(&g_zsum[dst], ex);
        atomicAdd(&g_cnt[dst], 1.f);
    }
}

// ---------------- kernel 3: normalize + scatter ----------------
__global__ void scatter_kernel(const int* __restrict__ ei, float* __restrict__ out) {
    int e = blockIdx.x * blockDim.x + threadIdx.x;
    if (e >= EN) return;
    int dst = __ldg(ei + EN + e);
    float ex = g_expv[e];
    float zs = g_zsum[dst];
    float c  = g_cnt[dst];
    float alpha = ex * fmaxf(c, 1.f) / zs;
    float attn = sqrtf(fmaxf(alpha, 0.f));
    float* op = out + (size_t)dst * 32;
    #pragma unroll
    for (int k = 0; k < 32; k++)
        atomicAdd(op + k, attn * g_vbuf[k * EN + e]);
}

// ---------------- launcher ----------------
extern "C" void kernel_launch(void* const* d_in, const int* in_sizes, int n_in,
                              void* d_out, int out_size) {
    const float* node_attr = (const float*)d_in[0];
    const int*   ei        = (const int*)  d_in[1];
    const float* edge_attr = (const float*)d_in[2];
    const float* edge_sh   = (const float*)d_in[3];
    const float* Wq0       = (const float*)d_in[4];
    const float* Wq1       = (const float*)d_in[5];
    const float* kW1       = (const float*)d_in[6];
    const float* kW2       = (const float*)d_in[7];
    const float* vW1       = (const float*)d_in[8];
    const float* vW2       = (const float*)d_in[9];
    const float* Wd0       = (const float*)d_in[10];
    const float* Wd1       = (const float*)d_in[11];
    float* out = (float*)d_out;

    zero_kernel<<<(NN * 32 + 255) / 256, 256>>>(out);
    node_kernel<<<(NN + 127) / 128, 128>>>(node_attr, Wq0, Wq1);
    edge_kernel<<<(EN + 255) / 256, 256>>>(node_attr, ei, edge_attr, edge_sh,
                                           kW1, kW2, vW1, vW2, Wd0, Wd1);
    scatter_kernel<<<(EN + 255) / 256, 256>>>(ei, out);
}